// round 12
// baseline (speedup 1.0000x reference)
#include <cuda_runtime.h>
#include <math.h>

#define B_   8192
#define L_   200
#define S_   81
#define SP_  84        /* padded row stride (floats) */
#define CEN_ 40
#define D_   128
#define H_   4
#define XSZ  (L_*S_)   /* 16200 floats per b */

// ---- scratch (device globals; no allocation allowed) ----
__device__ float g_R[(size_t)B_*H_*L_];
__device__ float g_c[(size_t)B_*H_];
__device__ float g_central[(size_t)B_*D_];
__device__ float g_Y[(size_t)B_*H_*L_];
__device__ float g_sur[(size_t)B_*D_];
__device__ float g_dummy;

// 3 no-op launches: ncu capture (4th launch) lands on kprep
__global__ void knop() { if (threadIdx.x == 0) g_dummy = 1.0f; }

// ============================================================
// kprep v4: double-buffered weight chunks (8 x k=25), grid 256,
// block 512. dyn smem = 19712 floats (78848 B)
//   XcT [200][32]          : sm[0..6400)
//   Wb  2 x [256][26]      : sm[6400..19712)
// ============================================================
#define KC_ 25
#define WBS_ 26            /* Wb row stride */

__global__ void __launch_bounds__(512, 2) kprep(
    const float* __restrict__ x,  const float* __restrict__ Wk,
    const float* __restrict__ bk, const float* __restrict__ Wv,
    const float* __restrict__ bv, const float* __restrict__ Wq,
    const float* __restrict__ bq)
{
    extern __shared__ float sm[];
    float* XcT = sm;           // [200][32]
    float* Wb0 = sm + 6400;    // [256][26]
    float* Wb1 = sm + 6400 + 256 * WBS_;
    const int tid = threadIdx.x;
    const int b0  = blockIdx.x * 32;
    const int w = tid >> 5, lane = tid & 31;

    // phase a: gather xs_center
    for (int idx = tid; idx < 32 * 200; idx += 512) {
        int bb = idx & 31, l = idx >> 5;
        XcT[l * 32 + bb] = x[(size_t)(b0 + bb) * XSZ + l * S_ + CEN_];
    }

    // preload weight chunk 0 (no sync needed before: different smem region)
    {
        const int dd = w * 16;   // each warp loads rows dd..dd+15, cols [0,25)
        #pragma unroll
        for (int r = 0; r < 16; r++) {
            int d = dd + r;
            const float* wr = (d < 128) ? (Wq + d * L_) : (Wv + (size_t)(d - 128) * L_);
            if (lane < KC_) Wb0[d * WBS_ + lane] = wr[lane];
        }
    }
    __syncthreads();

    // phase b: 32b x 256d GEMM, thread tile 4b x 4d, pipelined chunks
    const int bi = tid & 7;
    const int dj = tid >> 3;
    float acc[4][4];
    #pragma unroll
    for (int v = 0; v < 4; v++)
        #pragma unroll
        for (int u = 0; u < 4; u++) acc[v][u] = 0.f;

    #pragma unroll
    for (int ch = 0; ch < 8; ch++) {
        float* cur = (ch & 1) ? Wb1 : Wb0;
        float* nxt = (ch & 1) ? Wb0 : Wb1;
        // prefetch next chunk (overlaps with compute below)
        if (ch < 7) {
            const int k0 = (ch + 1) * KC_;
            const int dd = w * 16;
            #pragma unroll
            for (int r = 0; r < 16; r++) {
                int d = dd + r;
                const float* wr = (d < 128) ? (Wq + d * L_) : (Wv + (size_t)(d - 128) * L_);
                if (lane < KC_) nxt[d * WBS_ + lane] = wr[k0 + lane];
            }
        }
        // compute on current chunk
        const int k0 = ch * KC_;
        #pragma unroll 5
        for (int kk = 0; kk < KC_; kk++) {
            float4 xa0 = *(const float4*)&XcT[(k0 + kk) * 32 + bi * 4];
            float xa[4] = {xa0.x, xa0.y, xa0.z, xa0.w};
            float wv4[4];
            #pragma unroll
            for (int u = 0; u < 4; u++) wv4[u] = cur[(dj * 4 + u) * WBS_ + kk];
            #pragma unroll
            for (int v = 0; v < 4; v++)
                #pragma unroll
                for (int u = 0; u < 4; u++)
                    acc[v][u] += xa[v] * wv4[u];
        }
        __syncthreads();
    }

    // epilogue: Q -> QT smem [128][32], central -> global
    float* QT = sm;  // XcT dead
    if (dj < 32) {
        #pragma unroll
        for (int u = 0; u < 4; u++) {
            int d = dj * 4 + u;
            float bqd = bq[d];
            #pragma unroll
            for (int v = 0; v < 4; v++)
                QT[d * 32 + bi * 4 + v] = acc[v][u] + bqd;
        }
    } else {
        #pragma unroll
        for (int u = 0; u < 4; u++) {
            int d = (dj - 32) * 4 + u;
            float bvd = bv[d];
            #pragma unroll
            for (int v = 0; v < 4; v++)
                g_central[(size_t)(b0 + bi * 4 + v) * D_ + d] = acc[v][u] + bvd;
        }
    }
    __syncthreads();

    // c[b,h] = q_h . bk_h
    if (tid < 128) {
        int bb = tid & 31, h = tid >> 5;
        float cacc = 0.f;
        for (int dd = 0; dd < 32; dd++)
            cacc += QT[(h * 32 + dd) * 32 + bb] * bk[h * 32 + dd];
        g_c[(size_t)(b0 + bb) * H_ + h] = cacc;
    }

    // phase c: R[b,h,l]. 16 warps = (bg = w>>2) x (h = w&3)
    float* Wkc = sm + 4096;    // [128][100]
    const int bg = w >> 2;
    const int h  = w & 3;
    for (int lc = 0; lc < 2; lc++) {
        __syncthreads();
        for (int idx = tid; idx < 12800; idx += 512) {
            int dd = idx / 100, ll = idx - dd * 100;
            Wkc[idx] = Wk[(size_t)dd * L_ + lc * 100 + ll];
        }
        __syncthreads();
        {
            float acc2[8][4];
            #pragma unroll
            for (int v = 0; v < 8; v++)
                #pragma unroll
                for (int jj = 0; jj < 4; jj++) acc2[v][jj] = 0.f;
            for (int d = 0; d < 32; d++) {
                float4 q0 = *(const float4*)&QT[(h * 32 + d) * 32 + bg * 8];
                float4 q1 = *(const float4*)&QT[(h * 32 + d) * 32 + bg * 8 + 4];
                float q8[8] = {q0.x, q0.y, q0.z, q0.w, q1.x, q1.y, q1.z, q1.w};
                float wk4[4];
                #pragma unroll
                for (int jj = 0; jj < 4; jj++) {
                    int ll = lane + 32 * jj;
                    wk4[jj] = (ll < 100) ? Wkc[(h * 32 + d) * 100 + ll] : 0.f;
                }
                #pragma unroll
                for (int v = 0; v < 8; v++)
                    #pragma unroll
                    for (int jj = 0; jj < 4; jj++)
                        acc2[v][jj] += q8[v] * wk4[jj];
            }
            #pragma unroll
            for (int jj = 0; jj < 4; jj++) {
                int ll = lane + 32 * jj;
                if (ll < 100) {
                    int l = lc * 100 + ll;
                    #pragma unroll
                    for (int v = 0; v < 8; v++)
                        g_R[(size_t)(b0 + bg * 8 + v) * (H_ * L_) + h * L_ + l] = acc2[v][jj];
                }
            }
        }
    }
}

// ============================================================
// kmain (R7 exact, unchanged): 384 threads, 3 CTAs/SM.
// dyn smem = 17940 floats (71760 B)
// ============================================================
__global__ void __launch_bounds__(384, 3) kmain(const float* __restrict__ x)
{
    extern __shared__ float sm[];
    float* xs = sm;            // [200][84]
    float* Rs = sm + 16800;    // [4][200]
    float* cs = Rs + 800;      // [4]
    float* sc = cs + 4;        // [4][84]
    const int tid = threadIdx.x;
    const size_t b = blockIdx.x;

    {
        const float* xg = x + b * XSZ + tid;
        int l = tid / 81;
        int s = tid - l * 81;
        int off = l * SP_ + s;
        #pragma unroll 6
        for (int it = 0; it < 42; ++it) {
            xs[off] = xg[it * 384];
            s += 60;
            if (s >= 81) { s -= 81; off += 399; }
            else         {           off += 396; }
        }
        if (tid < 72) xs[off] = xg[42 * 384];

        if (tid < 200) {
            xs[tid * SP_ + 81] = 0.f;
            xs[tid * SP_ + 82] = 0.f;
            xs[tid * SP_ + 83] = 0.f;
        }
        for (int i = tid; i < 800; i += 384)
            Rs[i] = g_R[b * 800 + i];
        if (tid < 4) cs[tid] = g_c[b * 4 + tid];
    }
    __syncthreads();

    if (tid < 96) {
        const int sq = tid >> 2;
        const int c  = tid & 3;
        const int s4 = (sq < 21) ? sq * 4 : 80;
        const float* xp = xs + c * 50 * SP_ + s4;
        const float* r0p = Rs + c * 50;
        float a[H_][4];
        #pragma unroll
        for (int h = 0; h < H_; h++)
            #pragma unroll
            for (int j = 0; j < 4; j++) a[h][j] = 0.f;
        #pragma unroll 5
        for (int l = 0; l < 50; l++) {
            float4 xv = *(const float4*)xp;
            float r0 = r0p[l], r1 = r0p[200 + l], r2 = r0p[400 + l], r3 = r0p[600 + l];
            a[0][0] += r0 * xv.x; a[0][1] += r0 * xv.y; a[0][2] += r0 * xv.z; a[0][3] += r0 * xv.w;
            a[1][0] += r1 * xv.x; a[1][1] += r1 * xv.y; a[1][2] += r1 * xv.z; a[1][3] += r1 * xv.w;
            a[2][0] += r2 * xv.x; a[2][1] += r2 * xv.y; a[2][2] += r2 * xv.z; a[2][3] += r2 * xv.w;
            a[3][0] += r3 * xv.x; a[3][1] += r3 * xv.y; a[3][2] += r3 * xv.z; a[3][3] += r3 * xv.w;
            xp += SP_;
        }
        const unsigned m = 0xffffffffu;
        #pragma unroll
        for (int h = 0; h < H_; h++)
            #pragma unroll
            for (int j = 0; j < 4; j++) {
                a[h][j] += __shfl_xor_sync(m, a[h][j], 1);
                a[h][j] += __shfl_xor_sync(m, a[h][j], 2);
            }
        if (c == 0 && sq < 21) {
            #pragma unroll
            for (int h = 0; h < H_; h++) {
                float ch = cs[h];
                float4 o;
                float* op = (float*)&o;
                #pragma unroll
                for (int j = 0; j < 4; j++) {
                    int s = sq * 4 + j;
                    float v = (a[h][j] + ch) * 0.0883883476483184405f;
                    if (s == CEN_) v += -1000000.0f;
                    if (s >= 81)  v = -INFINITY;
                    op[j] = v;
                }
                *(float4*)&sc[h * SP_ + sq * 4] = o;
            }
        }
    }
    __syncthreads();

    const int wid = tid >> 5, lane = tid & 31;
    if (wid < 4) {
        float v0 = sc[wid * SP_ + lane];
        float v1 = sc[wid * SP_ + 32 + lane];
        float v2 = (lane < 20) ? sc[wid * SP_ + 64 + lane] : -INFINITY;
        float mx = fmaxf(v0, fmaxf(v1, v2));
        #pragma unroll
        for (int o = 16; o > 0; o >>= 1) mx = fmaxf(mx, __shfl_xor_sync(0xffffffffu, mx, o));
        float e0 = __expf(v0 - mx), e1 = __expf(v1 - mx);
        float e2 = (lane < 20 && v2 > -INFINITY) ? __expf(v2 - mx) : 0.f;
        float s3 = e0 + e1 + e2;
        #pragma unroll
        for (int o = 16; o > 0; o >>= 1) s3 += __shfl_xor_sync(0xffffffffu, s3, o);
        float rs = 1.f / s3;
        sc[wid * SP_ + lane] = e0 * rs;
        sc[wid * SP_ + 32 + lane] = e1 * rs;
        if (lane < 20) sc[wid * SP_ + 64 + lane] = e2 * rs;
    }
    __syncthreads();

    if (tid < 200) {
        const float* xr = xs + tid * SP_;
        float a0 = 0.f, a1 = 0.f, a2 = 0.f, a3 = 0.f;
        #pragma unroll 7
        for (int c = 0; c < 21; c++) {
            float4 xv = *(const float4*)&xr[c * 4];
            float4 t0 = *(const float4*)&sc[0 * SP_ + c * 4];
            float4 t1 = *(const float4*)&sc[1 * SP_ + c * 4];
            float4 t2 = *(const float4*)&sc[2 * SP_ + c * 4];
            float4 t3 = *(const float4*)&sc[3 * SP_ + c * 4];
            a0 += t0.x * xv.x + t0.y * xv.y + t0.z * xv.z + t0.w * xv.w;
            a1 += t1.x * xv.x + t1.y * xv.y + t1.z * xv.z + t1.w * xv.w;
            a2 += t2.x * xv.x + t2.y * xv.y + t2.z * xv.z + t2.w * xv.w;
            a3 += t3.x * xv.x + t3.y * xv.y + t3.z * xv.z + t3.w * xv.w;
        }
        float* Yb = g_Y + b * 800;
        Yb[tid] = a0; Yb[200 + tid] = a1; Yb[400 + tid] = a2; Yb[600 + tid] = a3;
    }
}

// ============================================================
// ksur v3 (unchanged): grid (256,4), 4 b per warp interleaved.
// block 256, dyn smem = 25728 B
// ============================================================
__global__ void __launch_bounds__(256) ksur(const float* __restrict__ Wv,
                                            const float* __restrict__ bv)
{
    extern __shared__ float sm[];
    float* Wvs = sm;            // [32][201]
    const int tid = threadIdx.x;
    const int b0 = blockIdx.x * 32;
    const int h  = blockIdx.y;
    const int lane = tid & 31, w = tid >> 5;

    for (int idx = tid; idx < 32 * 200; idx += 256) {
        int dd = idx / 200, ll = idx - dd * 200;
        Wvs[dd * 201 + ll] = Wv[(size_t)(h * 32 + dd) * L_ + ll];
    }
    __syncthreads();

    const float* wrow = Wvs + lane * 201;
    const float bvd = bv[h * 32 + lane];
    const unsigned m = 0xffffffffu;

    float yr[4][7];
    #pragma unroll
    for (int i = 0; i < 4; i++) {
        const float* yp = g_Y + (size_t)(b0 + i * 8 + w) * 800 + h * 200;
        #pragma unroll
        for (int t = 0; t < 6; t++) yr[i][t] = yp[lane + 32 * t];
        yr[i][6] = (lane < 8) ? yp[192 + lane] : 0.f;
    }

    float acc[4] = {0.f, 0.f, 0.f, 0.f};
    #pragma unroll
    for (int t = 0; t < 6; t++) {
        #pragma unroll
        for (int j = 0; j < 32; j++) {
            float wv = wrow[t * 32 + j];
            acc[0] += wv * __shfl_sync(m, yr[0][t], j);
            acc[1] += wv * __shfl_sync(m, yr[1][t], j);
            acc[2] += wv * __shfl_sync(m, yr[2][t], j);
            acc[3] += wv * __shfl_sync(m, yr[3][t], j);
        }
    }
    #pragma unroll
    for (int j = 0; j < 8; j++) {
        float wv = wrow[192 + j];
        acc[0] += wv * __shfl_sync(m, yr[0][6], j);
        acc[1] += wv * __shfl_sync(m, yr[1][6], j);
        acc[2] += wv * __shfl_sync(m, yr[2][6], j);
        acc[3] += wv * __shfl_sync(m, yr[3][6], j);
    }

    #pragma unroll
    for (int i = 0; i < 4; i++)
        g_sur[(size_t)(b0 + i * 8 + w) * D_ + h * 32 + lane] = acc[i] + bvd;
}

// ============================================================
// kgate (expf -> __expf)
// ============================================================
__global__ void __launch_bounds__(256) kgate(const float* __restrict__ Wg,
                                             const float* __restrict__ bg,
                                             float* __restrict__ out)
{
    const int lane = threadIdx.x & 31, w = threadIdx.x >> 5;
    const int b = blockIdx.x * 8 + w;
    float4 c4 = *(const float4*)&g_central[(size_t)b * D_ + lane * 4];
    float4 s4 = *(const float4*)&g_sur[(size_t)b * D_ + lane * 4];
    float4 w4 = *(const float4*)&Wg[lane * 4];
    float dot = (c4.x - s4.x) * w4.x + (c4.y - s4.y) * w4.y +
                (c4.z - s4.z) * w4.z + (c4.w - s4.w) * w4.w;
    #pragma unroll
    for (int o = 16; o > 0; o >>= 1) dot += __shfl_xor_sync(0xffffffffu, dot, o);
    float g = 1.f / (1.f + __expf(-(dot + bg[0])));
    float4 o4;
    o4.x = c4.x + g * s4.x; o4.y = c4.y + g * s4.y;
    o4.z = c4.z + g * s4.z; o4.w = c4.w + g * s4.w;
    *(float4*)&out[(size_t)b * D_ + lane * 4] = o4;
}

extern "C" void kernel_launch(void* const* d_in, const int* in_sizes, int n_in,
                              void* d_out, int out_size)
{
    const float* x  = (const float*)d_in[0];
    const float* Wk = (const float*)d_in[1];
    const float* bk = (const float*)d_in[2];
    const float* Wv = (const float*)d_in[3];
    const float* bv = (const float*)d_in[4];
    const float* Wq = (const float*)d_in[5];
    const float* bq = (const float*)d_in[6];
    const float* Wg = (const float*)d_in[7];
    const float* bg = (const float*)d_in[8];
    float* out = (float*)d_out;

    cudaFuncSetAttribute(kprep, cudaFuncAttributeMaxDynamicSharedMemorySize, 78848);
    cudaFuncSetAttribute(kmain, cudaFuncAttributeMaxDynamicSharedMemorySize, 71760);
    cudaFuncSetAttribute(ksur,  cudaFuncAttributeMaxDynamicSharedMemorySize, 25728);

    // 3 knops: ncu capture (4th launch) lands on kprep
    knop<<<1, 32>>>();
    knop<<<1, 32>>>();
    knop<<<1, 32>>>();
    kprep<<<256, 512, 78848>>>(x, Wk, bk, Wv, bv, Wq, bq);
    kmain<<<8192, 384, 71760>>>(x);
    ksur<<<dim3(256, 4), 256, 25728>>>(Wv, bv);
    kgate<<<1024, 256>>>(Wg, bg, out);
}